// round 5
// baseline (speedup 1.0000x reference)
#include <cuda_runtime.h>
#include <math.h>

#define BB   32
#define TT   512
#define LAT  256
#define HID  1024
#define HO   512
#define G3   1536
#define MTOT (BB*TT)
#define NCTA 128

// ---------------- scratch (device globals; no allocations allowed) ----------
__device__ float g_fc[BB*HID];                 // relu(z @ fc_w^T + fc_b)
__device__ float g_gx[(size_t)MTOT*G3];        // input-projection output (per layer, reused)
__device__ float g_y0[(size_t)MTOT*HO];        // layer0 output
__device__ float g_y1[(size_t)MTOT*HO];        // layer1 output
__device__ float g_h[2][BB*HO];                // double-buffered hidden state
__device__ volatile unsigned int g_gen;        // grid barrier generation
__device__ unsigned int g_cnt;                 // grid barrier arrival count

__device__ __forceinline__ float sigf(float x) { return 1.0f / (1.0f + expf(-x)); }

// Sense-reversing grid barrier. Safe because all NCTA CTAs are guaranteed
// co-resident (grid=128 <= 148 SMs; 256 thr / ~38KB smem / <64 regs per CTA).
__device__ __forceinline__ void grid_barrier() {
    __syncthreads();
    if (threadIdx.x == 0) {
        __threadfence();                      // release this CTA's writes
        unsigned int gen = g_gen;
        if (atomicAdd(&g_cnt, 1u) == NCTA - 1u) {
            g_cnt = 0u;
            __threadfence();
            g_gen = gen + 1u;
        } else {
            while (g_gen == gen) { }
        }
        __threadfence();                      // acquire other CTAs' writes
    }
    __syncthreads();
}

// ---------------- FC + ReLU:  g_fc[b,h] = relu(z[b,:] . fc_w[h,:] + fc_b[h]) -
__global__ void fc_kernel(const float* __restrict__ z,
                          const float* __restrict__ fc_w,
                          const float* __restrict__ fc_b) {
    __shared__ float zs[LAT];
    int b = blockIdx.x;
    zs[threadIdx.x] = z[b*LAT + threadIdx.x];
    __syncthreads();
    for (int h = threadIdx.x; h < HID; h += blockDim.x) {
        const float4* w = (const float4*)(fc_w + (size_t)h*LAT);
        float s = fc_b[h];
        #pragma unroll 8
        for (int k = 0; k < LAT/4; k++) {
            float4 wv = w[k];
            float4 zv = *(const float4*)(zs + 4*k);
            s += wv.x*zv.x + wv.y*zv.y + wv.z*zv.z + wv.w*zv.w;
        }
        g_fc[b*HID + h] = fmaxf(s, 0.0f);
    }
}

// ---------------- Input projection GEMM (NT):  g_gx = A @ W^T + bias --------
// MODE 0: A[m,k] = g_fc[b,k] + 0.01*chord[m,k], K=HID (layer 0, fused)
// MODE 1: A = g_y0, K=HO   (layer 1)
// MODE 2: A = g_y1, K=HO   (layer 2)
template<int MODE>
__global__ void __launch_bounds__(256) gemm_nt(const float* __restrict__ chord,
                                               const float* __restrict__ W,
                                               const float* __restrict__ bias) {
    constexpr int K = (MODE == 0) ? HID : HO;
    __shared__ float As[8][128];
    __shared__ float Bs[8][132];   // padded vs bank conflicts
    const float* A = (MODE == 1) ? g_y0 : (MODE == 2) ? g_y1 : g_fc;
    int bm = blockIdx.y * 128, bn = blockIdx.x * 128;
    int tid = threadIdx.x;
    int lm = tid >> 1, lk = (tid & 1) * 4;        // tile loader coords
    int tr = (tid >> 4) * 8, tc = (tid & 15) * 8; // 8x8 microtile coords
    float acc[8][8] = {};
    for (int k0 = 0; k0 < K; k0 += 8) {
        float4 av;
        if (MODE == 0) {
            int m = bm + lm;                       // m = b*TT + t
            float4 f = *(const float4*)(g_fc + (size_t)(m >> 9)*HID + k0 + lk);
            float4 c = *(const float4*)(chord + (size_t)m*HID + k0 + lk);
            av.x = f.x + 0.01f*c.x; av.y = f.y + 0.01f*c.y;
            av.z = f.z + 0.01f*c.z; av.w = f.w + 0.01f*c.w;
        } else {
            av = *(const float4*)(A + (size_t)(bm + lm)*K + k0 + lk);
        }
        float4 bv = *(const float4*)(W + (size_t)(bn + lm)*K + k0 + lk);
        As[lk+0][lm] = av.x; As[lk+1][lm] = av.y; As[lk+2][lm] = av.z; As[lk+3][lm] = av.w;
        Bs[lk+0][lm] = bv.x; Bs[lk+1][lm] = bv.y; Bs[lk+2][lm] = bv.z; Bs[lk+3][lm] = bv.w;
        __syncthreads();
        #pragma unroll
        for (int kk = 0; kk < 8; kk++) {
            float ar[8], br[8];
            *(float4*)&ar[0] = *(const float4*)&As[kk][tr];
            *(float4*)&ar[4] = *(const float4*)&As[kk][tr+4];
            *(float4*)&br[0] = *(const float4*)&Bs[kk][tc];
            *(float4*)&br[4] = *(const float4*)&Bs[kk][tc+4];
            #pragma unroll
            for (int i = 0; i < 8; i++)
                #pragma unroll
                for (int j = 0; j < 8; j++)
                    acc[i][j] += ar[i]*br[j];
        }
        __syncthreads();
    }
    for (int i = 0; i < 8; i++) {
        int row = bm + tr + i;
        float* cp = g_gx + (size_t)row*G3 + bn + tc;
        const float* bp = bias + bn + tc;
        #pragma unroll
        for (int j = 0; j < 8; j++) cp[j] = acc[i][j] + bp[j];
    }
}

// ---------------- Persistent GRU layer -------------------------------------
// 128 CTAs, each owns 4 hidden units j (all 3 gates -> 12 rows of w_hh in SMEM).
// Per step: gh = h @ w_hh^T (+b_hh) on its 12 rows x 32 batches, gate math,
// write h_new into the other h buffer + y, then one grid barrier.
// dst_mode: 0 -> g_y0, 1 -> g_y1, 2 -> dout (with seq_len mask).
__global__ void __launch_bounds__(256) gru_kernel(const float* __restrict__ w_hh,
                                                  const float* __restrict__ b_hh,
                                                  float* __restrict__ dout,
                                                  const int* __restrict__ seq_lens,
                                                  int dst_mode) {
    __shared__ float w_sm[12*HO];     // 24 KB
    __shared__ float red[8*12*32];    // 12 KB  per-warp partials
    __shared__ float gh_sm[12*32];    // 1.5 KB reduced gh
    int tid = threadIdx.x, lane = tid & 31, warp = tid >> 5;
    int jbase = blockIdx.x * 4;
    float* y = (dst_mode == 0) ? g_y0 : (dst_mode == 1) ? g_y1 : dout;

    // stage this CTA's 12 w_hh rows: gl = gate*4 + jj -> row gate*HO + jbase + jj
    for (int i = tid; i < 12*HO; i += 256) {
        int gl = i >> 9, k = i & (HO-1);
        int gate = gl >> 2, jj = gl & 3;
        w_sm[i] = w_hh[(size_t)(gate*HO + jbase + jj)*HO + k];
    }
    // zero h buffer 0 (this CTA's slice)
    if (tid < 128) {
        int b = tid >> 2, jj = tid & 3;
        g_h[0][b*HO + jbase + jj] = 0.0f;
    }
    __threadfence();
    grid_barrier();   // includes __syncthreads -> w_sm visible too

    const int k0 = warp * 64;   // each warp covers 64 of K=512
    for (int t = 0; t < TT; t++) {
        const float* hbuf = g_h[t & 1];
        // partial gh over this warp's k-slice; lane = batch b
        float acc[12] = {};
        #pragma unroll
        for (int kc = 0; kc < 64; kc += 4) {
            float4 hv = *(const float4*)(hbuf + lane*HO + k0 + kc);
            #pragma unroll
            for (int g = 0; g < 12; g++) {
                float4 wv = *(const float4*)(w_sm + g*HO + k0 + kc);
                acc[g] += hv.x*wv.x + hv.y*wv.y + hv.z*wv.z + hv.w*wv.w;
            }
        }
        #pragma unroll
        for (int g = 0; g < 12; g++) red[(warp*12 + g)*32 + lane] = acc[g];
        __syncthreads();
        // reduce 8 warps' partials -> gh_sm[gl][b] (+ bias)
        for (int o = tid; o < 384; o += 256) {
            int gl = o >> 5, b = o & 31;
            float s = 0.0f;
            #pragma unroll
            for (int w = 0; w < 8; w++) s += red[(w*12 + gl)*32 + b];
            int gate = gl >> 2, jj = gl & 3;
            gh_sm[gl*32 + b] = s + b_hh[gate*HO + jbase + jj];
        }
        __syncthreads();
        // gate math: 4 j * 32 b = 128 outputs
        if (tid < 128) {
            int jj = tid >> 5, b = tid & 31;
            int j = jbase + jj;
            size_t base = ((size_t)b*TT + t)*G3;
            float ghr = gh_sm[jj*32 + b];
            float ghz = gh_sm[(4 + jj)*32 + b];
            float ghn = gh_sm[(8 + jj)*32 + b];
            float r  = sigf(g_gx[base + j] + ghr);
            float zg = sigf(g_gx[base + HO + j] + ghz);
            float n  = tanhf(g_gx[base + 2*HO + j] + r*ghn);
            float hp = hbuf[b*HO + j];
            float hn2 = (1.0f - zg)*n + zg*hp;
            g_h[(t + 1) & 1][b*HO + j] = hn2;
            float yv = hn2;
            if (dst_mode == 2 && t >= seq_lens[b]) yv = 0.0f;
            y[((size_t)b*TT + t)*HO + j] = yv;
        }
        __threadfence();
        grid_barrier();
    }
}

// ---------------- launch ----------------------------------------------------
extern "C" void kernel_launch(void* const* d_in, const int* in_sizes, int n_in,
                              void* d_out, int out_size) {
    const float* z     = (const float*)d_in[0];
    const int*   seq   = (const int*)  d_in[1];
    const float* chord = (const float*)d_in[2];
    const float* fc_w  = (const float*)d_in[3];
    const float* fc_b  = (const float*)d_in[4];
    const float* w_ih0 = (const float*)d_in[5];
    const float* w_hh0 = (const float*)d_in[6];
    const float* b_ih0 = (const float*)d_in[7];
    const float* b_hh0 = (const float*)d_in[8];
    const float* w_ih1 = (const float*)d_in[9];
    const float* w_hh1 = (const float*)d_in[10];
    const float* b_ih1 = (const float*)d_in[11];
    const float* b_hh1 = (const float*)d_in[12];
    const float* w_ih2 = (const float*)d_in[13];
    const float* w_hh2 = (const float*)d_in[14];
    const float* b_ih2 = (const float*)d_in[15];
    const float* b_hh2 = (const float*)d_in[16];
    float* out = (float*)d_out;

    dim3 ggrid(G3/128, MTOT/128);   // (12, 128)

    fc_kernel<<<BB, LAT>>>(z, fc_w, fc_b);

    gemm_nt<0><<<ggrid, 256>>>(chord, w_ih0, b_ih0);
    gru_kernel<<<NCTA, 256>>>(w_hh0, b_hh0, nullptr, seq, 0);

    gemm_nt<1><<<ggrid, 256>>>(nullptr, w_ih1, b_ih1);
    gru_kernel<<<NCTA, 256>>>(w_hh1, b_hh1, nullptr, seq, 1);

    gemm_nt<2><<<ggrid, 256>>>(nullptr, w_ih2, b_ih2);
    gru_kernel<<<NCTA, 256>>>(w_hh2, b_hh2, out, seq, 2);
}

// round 6
// speedup vs baseline: 1.4710x; 1.4710x over previous
#include <cuda_runtime.h>
#include <math.h>

#define BB   32
#define TT   512
#define LAT  256
#define HID  1024
#define HO   512
#define G3   1536
#define MTOT (BB*TT)

// GRU partitioning: 4 independent groups x 8 batches, 32 CTAs per group.
#define NG   4
#define CPG  32
#define BPG  8
#define JPC  16          // j values per CTA
#define GROWS 48         // rows per CTA = JPC * 3 gates
#define WP   516         // padded row stride (floats) for w_sm  (bank-tiling)
#define HP   516         // padded row stride for h_sm

// ---------------- scratch (device globals; no allocations allowed) ----------
__device__ float g_fc[BB*HID];                 // relu(z @ fc_w^T + fc_b)
__device__ float g_gx[(size_t)MTOT*G3];        // input-projection output (reused per layer)
__device__ float g_y0[(size_t)MTOT*HO];        // layer0 output
__device__ float g_y1[(size_t)MTOT*HO];        // layer1 output
__device__ float g_h2[NG][2][BPG*HO];          // per-group double-buffered hidden state
__device__ unsigned int g_cnt2[NG];            // per-group barrier count
__device__ volatile unsigned int g_gen2[NG];   // per-group barrier generation

__device__ __forceinline__ float sigf(float x) { return 1.0f / (1.0f + expf(-x)); }

// Sense-reversing barrier over the CPG CTAs of one group. All 128 CTAs are
// co-resident (1 CTA/SM, 128 <= 148 SMs), so spinning is safe.
__device__ __forceinline__ void group_barrier(int grp) {
    __syncthreads();
    if (threadIdx.x == 0) {
        __threadfence();                      // release this CTA's writes
        unsigned int gen = g_gen2[grp];
        if (atomicAdd(&g_cnt2[grp], 1u) == CPG - 1u) {
            g_cnt2[grp] = 0u;
            __threadfence();
            g_gen2[grp] = gen + 1u;
        } else {
            while (g_gen2[grp] == gen) { }
        }
        __threadfence();                      // acquire other CTAs' writes
    }
    __syncthreads();
}

// ---------------- FC + ReLU:  g_fc[b,h] = relu(z[b,:] . fc_w[h,:] + fc_b[h]) -
__global__ void fc_kernel(const float* __restrict__ z,
                          const float* __restrict__ fc_w,
                          const float* __restrict__ fc_b) {
    __shared__ float zs[LAT];
    int b = blockIdx.x;
    zs[threadIdx.x] = z[b*LAT + threadIdx.x];
    __syncthreads();
    for (int h = threadIdx.x; h < HID; h += blockDim.x) {
        const float4* w = (const float4*)(fc_w + (size_t)h*LAT);
        float s = fc_b[h];
        #pragma unroll 8
        for (int k = 0; k < LAT/4; k++) {
            float4 wv = w[k];
            float4 zv = *(const float4*)(zs + 4*k);
            s += wv.x*zv.x + wv.y*zv.y + wv.z*zv.z + wv.w*zv.w;
        }
        g_fc[b*HID + h] = fmaxf(s, 0.0f);
    }
}

// ---------------- Input projection GEMM (NT):  g_gx = A @ W^T + bias --------
template<int MODE>
__global__ void __launch_bounds__(256) gemm_nt(const float* __restrict__ chord,
                                               const float* __restrict__ W,
                                               const float* __restrict__ bias) {
    constexpr int K = (MODE == 0) ? HID : HO;
    __shared__ float As[8][128];
    __shared__ float Bs[8][132];
    const float* A = (MODE == 1) ? g_y0 : (MODE == 2) ? g_y1 : g_fc;
    int bm = blockIdx.y * 128, bn = blockIdx.x * 128;
    int tid = threadIdx.x;
    int lm = tid >> 1, lk = (tid & 1) * 4;
    int tr = (tid >> 4) * 8, tc = (tid & 15) * 8;
    float acc[8][8] = {};
    for (int k0 = 0; k0 < K; k0 += 8) {
        float4 av;
        if (MODE == 0) {
            int m = bm + lm;
            float4 f = *(const float4*)(g_fc + (size_t)(m >> 9)*HID + k0 + lk);
            float4 c = *(const float4*)(chord + (size_t)m*HID + k0 + lk);
            av.x = f.x + 0.01f*c.x; av.y = f.y + 0.01f*c.y;
            av.z = f.z + 0.01f*c.z; av.w = f.w + 0.01f*c.w;
        } else {
            av = *(const float4*)(A + (size_t)(bm + lm)*K + k0 + lk);
        }
        float4 bv = *(const float4*)(W + (size_t)(bn + lm)*K + k0 + lk);
        As[lk+0][lm] = av.x; As[lk+1][lm] = av.y; As[lk+2][lm] = av.z; As[lk+3][lm] = av.w;
        Bs[lk+0][lm] = bv.x; Bs[lk+1][lm] = bv.y; Bs[lk+2][lm] = bv.z; Bs[lk+3][lm] = bv.w;
        __syncthreads();
        #pragma unroll
        for (int kk = 0; kk < 8; kk++) {
            float ar[8], br[8];
            *(float4*)&ar[0] = *(const float4*)&As[kk][tr];
            *(float4*)&ar[4] = *(const float4*)&As[kk][tr+4];
            *(float4*)&br[0] = *(const float4*)&Bs[kk][tc];
            *(float4*)&br[4] = *(const float4*)&Bs[kk][tc+4];
            #pragma unroll
            for (int i = 0; i < 8; i++)
                #pragma unroll
                for (int j = 0; j < 8; j++)
                    acc[i][j] += ar[i]*br[j];
        }
        __syncthreads();
    }
    for (int i = 0; i < 8; i++) {
        int row = bm + tr + i;
        float* cp = g_gx + (size_t)row*G3 + bn + tc;
        const float* bp = bias + bn + tc;
        #pragma unroll
        for (int j = 0; j < 8; j++) cp[j] = acc[i][j] + bp[j];
    }
}

// ---------------- Persistent GRU layer, batch-group version -----------------
// Grid = 128 CTAs = 4 groups x 32 CTAs. Group g owns batches [g*8, g*8+8) and
// syncs ONLY within the group (32 arrivals, independent of other groups).
// Each CTA owns 16 j values (48 w_hh rows, fp32, in SMEM). Per step:
//   1. stage the group's h[8,512] into SMEM (coalesced),
//   2. register-tiled GEMV: thread = (rowgrp rg in 0..7, k-slice ks in 0..31),
//      microtile 6 rows x 8 batches, rows gl = rg + 8u  (bank-conflict free),
//   3. smem reduce over 32 k-slices, + bias,
//   4. gate math on 128 threads (gx prefetched before the GEMV),
//   5. group barrier (skipped on the last step).
__global__ void __launch_bounds__(256) gru2(const float* __restrict__ whh,
                                            const float* __restrict__ bhh,
                                            float* __restrict__ dout,
                                            const int* __restrict__ seq_lens,
                                            int dst_mode) {
    extern __shared__ float sm[];
    float* w_sm  = sm;                       // GROWS * WP          = 24768
    float* h_sm  = w_sm + GROWS*WP;          // BPG * HP            =  4128
    float* red   = h_sm + BPG*HP;            // 32 * 8 * 48         = 12288
    float* gh_sm = red + 32*8*GROWS;         // GROWS * 9           =   432
    float* bh_sm = gh_sm + GROWS*9;          // GROWS               =    48

    float* y = (dst_mode == 0) ? g_y0 : (dst_mode == 1) ? g_y1 : dout;

    int tid = threadIdx.x;
    int grp = blockIdx.x >> 5;
    int cig = blockIdx.x & 31;
    int jbase = cig * JPC;

    // stage this CTA's 48 w_hh rows (row gl = gate*16 + jj)
    for (int i = tid; i < GROWS*HO; i += 256) {
        int gl = i >> 9, k = i & (HO-1);
        int gate = gl >> 4, jj = gl & 15;
        w_sm[gl*WP + k] = whh[(size_t)(gate*HO + jbase + jj)*HO + k];
    }
    if (tid < GROWS) bh_sm[tid] = bhh[(tid >> 4)*HO + jbase + (tid & 15)];

    const int ks = tid >> 3;        // k-slice 0..31 (16 k each)
    const int rg = tid & 7;         // row group 0..7
    const int k0 = ks * 16;
    // gate-math coords (threads 0..127)
    const int gjj = tid & 15, gb = tid >> 4;
    const int b_glob = grp*BPG + gb;
    int slen = TT;
    if (dst_mode == 2 && tid < 128) slen = seq_lens[b_glob];
    __syncthreads();

    for (int t = 0; t < TT; t++) {
        // ---- stage h for this group's 8 batches ----
        if (t == 0) {
            for (int i = tid; i < BPG*HO; i += 256)
                h_sm[(i >> 9)*HP + (i & (HO-1))] = 0.0f;
        } else {
            const float* hb = g_h2[grp][t & 1];
            for (int i = tid*4; i < BPG*HO; i += 1024) {
                float4 v = *(const float4*)(hb + i);
                *(float4*)(h_sm + (i >> 9)*HP + (i & (HO-1))) = v;
            }
        }
        __syncthreads();

        // ---- prefetch gx operands (independent of h) ----
        float gxr = 0.f, gxz = 0.f, gxn = 0.f;
        if (tid < 128) {
            size_t base = ((size_t)b_glob*TT + t)*G3 + jbase + gjj;
            gxr = g_gx[base];
            gxz = g_gx[base + HO];
            gxn = g_gx[base + 2*HO];
        }

        // ---- GEMV partials: 6 rows x 8 batches, 16 k per thread ----
        float acc[6][8];
        #pragma unroll
        for (int u = 0; u < 6; u++)
            #pragma unroll
            for (int v = 0; v < 8; v++) acc[u][v] = 0.0f;

        #pragma unroll
        for (int kc = 0; kc < 16; kc += 4) {
            float4 w4[6];
            #pragma unroll
            for (int u = 0; u < 6; u++)
                w4[u] = *(const float4*)(w_sm + (rg + 8*u)*WP + k0 + kc);
            #pragma unroll
            for (int v = 0; v < 8; v++) {
                float4 h4 = *(const float4*)(h_sm + v*HP + k0 + kc);
                #pragma unroll
                for (int u = 0; u < 6; u++) {
                    acc[u][v] += w4[u].x*h4.x + w4[u].y*h4.y
                               + w4[u].z*h4.z + w4[u].w*h4.w;
                }
            }
        }
        #pragma unroll
        for (int u = 0; u < 6; u++)
            #pragma unroll
            for (int v = 0; v < 8; v++)
                red[(ks*8 + rg)*GROWS + u*8 + v] = acc[u][v];
        __syncthreads();

        // ---- reduce 32 k-slices -> gh_sm[gl][b] (+bias) ----
        for (int o = tid; o < 8*GROWS; o += 256) {
            int pos = o / GROWS, idx = o - pos*GROWS;   // pos = rg
            float s = 0.0f;
            #pragma unroll 8
            for (int ksi = 0; ksi < 32; ksi++)
                s += red[(ksi*8 + pos)*GROWS + idx];
            int u = idx >> 3, v = idx & 7;
            int gl = pos + 8*u;
            gh_sm[gl*9 + v] = s + bh_sm[gl];
        }
        __syncthreads();

        // ---- gate math: 16 j x 8 b = 128 outputs ----
        if (tid < 128) {
            float ghr = gh_sm[(     gjj)*9 + gb];
            float ghz = gh_sm[(16 + gjj)*9 + gb];
            float ghn = gh_sm[(32 + gjj)*9 + gb];
            float r  = sigf(gxr + ghr);
            float zg = sigf(gxz + ghz);
            float n  = tanhf(gxn + r*ghn);
            float hp = h_sm[gb*HP + jbase + gjj];
            float hn2 = (1.0f - zg)*n + zg*hp;
            g_h2[grp][(t + 1) & 1][gb*HO + jbase + gjj] = hn2;
            float yv = (t < slen) ? hn2 : 0.0f;
            y[((size_t)b_glob*TT + t)*HO + jbase + gjj] = yv;
        }

        if (t < TT - 1) group_barrier(grp);
    }
}

// ---------------- launch ----------------------------------------------------
#define GRU_SMEM ((GROWS*WP + BPG*HP + 32*8*GROWS + GROWS*9 + GROWS) * 4)

extern "C" void kernel_launch(void* const* d_in, const int* in_sizes, int n_in,
                              void* d_out, int out_size) {
    const float* z     = (const float*)d_in[0];
    const int*   seq   = (const int*)  d_in[1];
    const float* chord = (const float*)d_in[2];
    const float* fc_w  = (const float*)d_in[3];
    const float* fc_b  = (const float*)d_in[4];
    const float* w_ih0 = (const float*)d_in[5];
    const float* w_hh0 = (const float*)d_in[6];
    const float* b_ih0 = (const float*)d_in[7];
    const float* b_hh0 = (const float*)d_in[8];
    const float* w_ih1 = (const float*)d_in[9];
    const float* w_hh1 = (const float*)d_in[10];
    const float* b_ih1 = (const float*)d_in[11];
    const float* b_hh1 = (const float*)d_in[12];
    const float* w_ih2 = (const float*)d_in[13];
    const float* w_hh2 = (const float*)d_in[14];
    const float* b_ih2 = (const float*)d_in[15];
    const float* b_hh2 = (const float*)d_in[16];
    float* out = (float*)d_out;

    cudaFuncSetAttribute(gru2, cudaFuncAttributeMaxDynamicSharedMemorySize, GRU_SMEM);

    dim3 ggrid(G3/128, MTOT/128);   // (12, 128)

    fc_kernel<<<BB, LAT>>>(z, fc_w, fc_b);

    gemm_nt<0><<<ggrid, 256>>>(chord, w_ih0, b_ih0);
    gru2<<<NG*CPG, 256, GRU_SMEM>>>(w_hh0, b_hh0, nullptr, seq, 0);

    gemm_nt<1><<<ggrid, 256>>>(nullptr, w_ih1, b_ih1);
    gru2<<<NG*CPG, 256, GRU_SMEM>>>(w_hh1, b_hh1, nullptr, seq, 1);

    gemm_nt<2><<<ggrid, 256>>>(nullptr, w_ih2, b_ih2);
    gru2<<<NG*CPG, 256, GRU_SMEM>>>(w_hh2, b_hh2, out, seq, 2);
}